// round 5
// baseline (speedup 1.0000x reference)
#include <cuda_runtime.h>
#include <cuda_bf16.h>
#include <cstdint>

#define B_SZ 1024
#define S_SZ 256
#define D_SZ 512
#define E_SZ 16
#define O_SZ 512

#define BM 128
#define BN 256
#define BK 64
#define KCHUNKS (D_SZ / BK)
#define NTHREADS 512
#define BTILE_BYTES 32768      /* 256 rows x 128B, SW128 image of one (ntile, kchunk) */

// Feature gate: defined only when codegen targets sm_103a (arch-specific pass).
#if defined(__CUDA_ARCH__) && defined(__CUDA_ARCH_FEAT_SM103_ALL)
#define USE_TCGEN05 1
#else
#define USE_TCGEN05 0
#endif

// ---------------- scratch (device globals; no allocation allowed) ----------------
// Tiled, pre-swizzled weights: [E][ntile=2][kchunk=8] blocks of 32KB (SMEM image).
__device__ __align__(128) unsigned char g_Wt_hi[E_SZ * 2 * KCHUNKS * BTILE_BYTES];
__device__ __align__(128) unsigned char g_Wt_lo[E_SZ * 2 * KCHUNKS * BTILE_BYTES];
__device__ int   g_idx[B_SZ];
__device__ float g_gate[B_SZ];

// ---------------- common helpers ----------------
__device__ __forceinline__ uint32_t smem_to_u32(const void* p) {
    uint32_t a;
    asm("{ .reg .u64 t; cvta.to.shared.u64 t, %1; cvt.u32.u64 %0, t; }" : "=r"(a) : "l"(p));
    return a;
}
#define SMEM_SWIZZLE_128B(o) ((o) ^ (((o) >> 3) & 0x70))

__device__ __forceinline__ uint32_t pack_bf16x2(__nv_bfloat16 a, __nv_bfloat16 b) {
    uint16_t au = __bfloat16_as_ushort(a);
    uint16_t bu = __bfloat16_as_ushort(b);
    return (uint32_t)au | ((uint32_t)bu << 16);
}

#define CP_ASYNC16(dst_u32, src_ptr) \
    asm volatile("cp.async.cg.shared.global [%0], [%1], 16;" :: "r"(dst_u32), "l"(src_ptr))
#define CP_ASYNC_COMMIT() asm volatile("cp.async.commit_group;" ::: "memory")
#define CP_ASYNC_WAIT_ALL() asm volatile("cp.async.wait_group 0;" ::: "memory")

// ---------------- SMEM layout (both paths) ----------------
// [0..16)   tmem ptr
// [16..80)  mbarriers: full0, full1, empty0, empty1
// [1024 .. 1024+2*98304) : two 96KB stages: A_HI 16K | A_LO 16K | B_HI 32K | B_LO 32K
// [197632 ..) bias (256 floats)
#define SMEM_TMEM_PTR 0
#define SMEM_FULL0    16
#define SMEM_FULL1    24
#define SMEM_EMPTY0   32
#define SMEM_EMPTY1   40
#define STAGE0_OFF    1024
#define STAGE_STRIDE  98304
#define OFF_AHI       0
#define OFF_ALO       16384
#define OFF_BHI       32768
#define OFF_BLO       65536
#define SMEM_BIAS     (STAGE0_OFF + 2 * STAGE_STRIDE)        // 197632
#define SMEM_TOTAL    (SMEM_BIAS + 1024 + 128)               // 198784

#if USE_TCGEN05
// ---------------- tcgen05 PTX helpers (sm_103a pass only) ----------------
__device__ __forceinline__ uint32_t elect_one_pred() {
    uint32_t pred;
    asm volatile(
        "{\n\t.reg .pred p;\n\t"
        "elect.sync _|p, 0xFFFFFFFF;\n\t"
        "selp.b32 %0, 1, 0, p;\n\t}"
        : "=r"(pred));
    return pred;
}
static constexpr uint64_t SMEM_DESC_BASE_SW128 =
    (uint64_t(2)  << 61) | (uint64_t(1) << 46) | (uint64_t(64) << 32) | (uint64_t(1) << 16);
#define MAKE_SMEM_DESC(base_addr) \
    (SMEM_DESC_BASE_SW128 | ((uint64_t)((base_addr) >> 4) & 0x3FFF))

#define TCGEN05_ALLOC(smem_result_addr, nCols) \
    asm volatile("tcgen05.alloc.cta_group::1.sync.aligned.shared::cta.b32 [%0], %1;" \
        :: "r"((uint32_t)(smem_result_addr)), "r"((uint32_t)(nCols)) : "memory")
#define TCGEN05_DEALLOC(tmem_addr, nCols) \
    asm volatile("tcgen05.dealloc.cta_group::1.sync.aligned.b32 %0, %1;" \
        :: "r"(tmem_addr), "r"((uint32_t)(nCols)))
#define TCGEN05_RELINQUISH_ALLOC_PERMIT() \
    asm volatile("tcgen05.relinquish_alloc_permit.cta_group::1.sync.aligned;")
#define TCGEN05_COMMIT(mbar_smem_addr) \
    asm volatile("tcgen05.commit.cta_group::1.mbarrier::arrive::one.shared::cluster.b64 [%0];" \
        :: "r"((uint32_t)(mbar_smem_addr)) : "memory")
#define TCGEN05_FENCE_AFTER() \
    asm volatile("tcgen05.fence::after_thread_sync;" ::: "memory")
#define TCGEN05_WAIT_LD() \
    asm volatile("tcgen05.wait::ld.sync.aligned;" ::: "memory")
#define FENCE_PROXY_ASYNC_SHARED_CTA() \
    asm volatile("fence.proxy.async.shared::cta;" ::: "memory")
#define MBARRIER_INIT(mbar_smem_addr, count) \
    asm volatile("mbarrier.init.shared.b64 [%0], %1;" \
        :: "r"((uint32_t)(mbar_smem_addr)), "r"((uint32_t)(count)) : "memory")
#define MBARRIER_ARRIVE(mbar_smem_addr) \
    asm volatile("mbarrier.arrive.shared.b64 _, [%0];" \
        :: "r"((uint32_t)(mbar_smem_addr)) : "memory")
#define MBARRIER_EXPECT_TX(mbar_smem_addr, tx_bytes) \
    asm volatile("mbarrier.arrive.expect_tx.shared.b64 _, [%0], %1;" \
        :: "r"((uint32_t)(mbar_smem_addr)), "r"((uint32_t)(tx_bytes)) : "memory")
#define CP_ASYNC_BULK_G2S(dst_u32, src_ptr, bytes, mbar) \
    asm volatile("cp.async.bulk.shared::cta.global.mbarrier::complete_tx::bytes [%0], [%1], %2, [%3];" \
        :: "r"((uint32_t)(dst_u32)), "l"(src_ptr), "r"((uint32_t)(bytes)), "r"((uint32_t)(mbar)) : "memory")
#define MBARRIER_WAIT_PARITY(mbar_smem_addr, phase_parity) do { \
    uint32_t _mbar = (uint32_t)(mbar_smem_addr); \
    uint32_t _parity = (uint32_t)(phase_parity); \
    uint32_t _done; \
    asm volatile( \
        "{\n\t.reg .pred p;\n\t" \
        "mbarrier.try_wait.parity.acquire.cta.shared::cta.b64 p, [%1], %2;\n\t" \
        "selp.b32 %0, 1, 0, p;\n\t}" \
        : "=r"(_done) : "r"(_mbar), "r"(_parity) : "memory"); \
    if (!_done) { \
        asm volatile( \
            "{\n\t.reg .pred P1;\n\t" \
            "WAIT_LOOP_%=:\n\t" \
            "mbarrier.try_wait.parity.acquire.cta.shared::cta.b64 P1, [%0], %1, 0x989680;\n\t" \
            "@P1 bra.uni WAIT_DONE_%=;\n\t" \
            "bra.uni WAIT_LOOP_%=;\n\t" \
            "WAIT_DONE_%=:\n\t}" \
            :: "r"(_mbar), "r"(_parity) : "memory"); \
    } \
} while(0)
#define TCGEN05_LD_32X32B_X32(r, tmem_addr) \
    asm volatile( \
        "tcgen05.ld.sync.aligned.32x32b.x32.b32 " \
        "{%0, %1, %2, %3, %4, %5, %6, %7, " \
        " %8, %9, %10, %11, %12, %13, %14, %15, " \
        " %16, %17, %18, %19, %20, %21, %22, %23, " \
        " %24, %25, %26, %27, %28, %29, %30, %31}, [%32];" \
        : "=r"((r)[0]),  "=r"((r)[1]),  "=r"((r)[2]),  "=r"((r)[3]), \
          "=r"((r)[4]),  "=r"((r)[5]),  "=r"((r)[6]),  "=r"((r)[7]), \
          "=r"((r)[8]),  "=r"((r)[9]),  "=r"((r)[10]), "=r"((r)[11]), \
          "=r"((r)[12]), "=r"((r)[13]), "=r"((r)[14]), "=r"((r)[15]), \
          "=r"((r)[16]), "=r"((r)[17]), "=r"((r)[18]), "=r"((r)[19]), \
          "=r"((r)[20]), "=r"((r)[21]), "=r"((r)[22]), "=r"((r)[23]), \
          "=r"((r)[24]), "=r"((r)[25]), "=r"((r)[26]), "=r"((r)[27]), \
          "=r"((r)[28]), "=r"((r)[29]), "=r"((r)[30]), "=r"((r)[31]) \
        : "r"(tmem_addr))

__device__ __forceinline__ void mma_f16_ss_cg1(uint32_t d_tmem, uint64_t a_desc,
                                               uint64_t b_desc, uint32_t idesc, bool acc) {
    uint32_t en = acc ? 1u : 0u;
    asm volatile(
        "{\n\t.reg .pred p;\n\t"
        "setp.ne.u32 p, %5, 0;\n\t"
        "tcgen05.mma.cta_group::1.kind::f16 [%0], %1, %2, %3, {%4, %4, %4, %4}, p;\n\t}"
        :: "r"(d_tmem), "l"(a_desc), "l"(b_desc), "r"(idesc), "r"(0u), "r"(en)
        : "memory");
}
static constexpr uint32_t MMA_IDESC =
    (1u << 4) | (1u << 7) | (1u << 10) | ((BN / 8) << 17) | ((BM / 16) << 24);
#endif  // USE_TCGEN05

// ---------------- fallback helpers (legal on plain sm_103) ----------------
#define LDSM_X4(r, addr) \
    asm volatile("ldmatrix.sync.aligned.m8n8.x4.shared.b16 {%0,%1,%2,%3}, [%4];" \
        : "=r"((r)[0]), "=r"((r)[1]), "=r"((r)[2]), "=r"((r)[3]) : "r"(addr))

#define MMA_BF16(d, a, b0, b1) \
    asm volatile("mma.sync.aligned.m16n8k16.row.col.f32.bf16.bf16.f32 " \
        "{%0,%1,%2,%3}, {%4,%5,%6,%7}, {%8,%9}, {%0,%1,%2,%3};" \
        : "+f"((d)[0]), "+f"((d)[1]), "+f"((d)[2]), "+f"((d)[3]) \
        : "r"((a)[0]), "r"((a)[1]), "r"((a)[2]), "r"((a)[3]), "r"(b0), "r"(b1))

// ================= gating: mean -> linear -> softmax -> argmax =================
__global__ void __launch_bounds__(512)
gating_kernel(const float* __restrict__ x,
              const float* __restrict__ Wg,
              const float* __restrict__ bg) {
    int b = blockIdx.x;
    int tid = threadIdx.x;            // 512 threads
    __shared__ float4 part[4][128];
    __shared__ float xm[D_SZ];
    __shared__ float logits[E_SZ];

    int grp = tid >> 7;
    int dq  = tid & 127;

    const float4* xp = reinterpret_cast<const float4*>(x + (size_t)b * S_SZ * D_SZ)
                       + (size_t)grp * (D_SZ / 4) + dq;
    float4 a = make_float4(0.f, 0.f, 0.f, 0.f);
#pragma unroll 16
    for (int s = 0; s < S_SZ / 4; s++) {
        float4 v = xp[(size_t)s * D_SZ];
        a.x += v.x; a.y += v.y; a.z += v.z; a.w += v.w;
    }
    part[grp][dq] = a;
    __syncthreads();

    if (tid < 128) {
        float4 p0 = part[0][tid], p1 = part[1][tid], p2 = part[2][tid], p3 = part[3][tid];
        const float inv = 1.0f / S_SZ;
        xm[tid * 4 + 0] = (p0.x + p1.x + p2.x + p3.x) * inv;
        xm[tid * 4 + 1] = (p0.y + p1.y + p2.y + p3.y) * inv;
        xm[tid * 4 + 2] = (p0.z + p1.z + p2.z + p3.z) * inv;
        xm[tid * 4 + 3] = (p0.w + p1.w + p2.w + p3.w) * inv;
    }
    __syncthreads();

    int wid = tid >> 5, lane = tid & 31;
    float p = 0.f;
    for (int d = lane; d < D_SZ; d += 32) p += xm[d] * Wg[d * E_SZ + wid];
#pragma unroll
    for (int o = 16; o; o >>= 1) p += __shfl_xor_sync(0xffffffffu, p, o);
    if (lane == 0) logits[wid] = p + bg[wid];
    __syncthreads();

    if (tid == 0) {
        float mx = logits[0]; int mi = 0;
#pragma unroll
        for (int e = 1; e < E_SZ; e++) if (logits[e] > mx) { mx = logits[e]; mi = e; }
        float den = 0.f;
#pragma unroll
        for (int e = 0; e < E_SZ; e++) den += expf(logits[e] - mx);
        g_idx[b]  = mi;
        g_gate[b] = 1.0f / den;
    }
}

// ====== convert We[E,D,O] fp32 -> tiled pre-swizzled bf16 hi/lo blocks ======
// Block (e, nt, c) is the exact SW128 SMEM image of B rows [nt*256, nt*256+256) x K [c*64, c*64+64).
__global__ void convert_w_kernel(const float* __restrict__ We) {
    __shared__ float tile[32][33];
    int e  = blockIdx.z;
    int d0 = blockIdx.y * 32;
    int o0 = blockIdx.x * 32;
    int tx = threadIdx.x, ty = threadIdx.y;   // 32 x 8

    const float* src = We + ((size_t)e * D_SZ + d0) * O_SZ + o0;
#pragma unroll
    for (int k = 0; k < 4; k++)
        tile[ty + 8 * k][tx] = src[(size_t)(ty + 8 * k) * O_SZ + tx];
    __syncthreads();

#pragma unroll
    for (int k = 0; k < 4; k++) {
        float v = tile[tx][ty + 8 * k];       // element (d = d0+tx, o = o0+ty+8k)
        __nv_bfloat16 hi = __float2bfloat16(v);
        float r = v - __bfloat162float(hi);
        __nv_bfloat16 lo = __float2bfloat16(r);

        int o  = o0 + ty + 8 * k;
        int d  = d0 + tx;
        int nt = o >> 8;
        int rr = o & 255;
        int c  = d >> 6;
        int dk = d & 63;
        size_t block = ((size_t)(e * 2 + nt) * KCHUNKS + c) * BTILE_BYTES;
        uint32_t off = SMEM_SWIZZLE_128B((uint32_t)(rr * 128 + dk * 2));
        *(__nv_bfloat16*)(g_Wt_hi + block + off) = hi;
        *(__nv_bfloat16*)(g_Wt_lo + block + off) = lo;
    }
}

#if !USE_TCGEN05
// fallback per-chunk compute: ldmatrix + 3x mma per (t, ntile)
__device__ __forceinline__ void fb_compute(uint32_t sA_hi, uint32_t sA_lo,
                                           uint32_t sB_hi, uint32_t sB_lo,
                                           int lane, int wm, int wn,
                                           float acc[2][8][4]) {
#pragma unroll
    for (int ks = 0; ks < 4; ks++) {
        uint32_t ah[2][4], al[2][4];
#pragma unroll
        for (int t = 0; t < 2; t++) {
            int row = wm * 32 + t * 16 + (lane & 15);
            int bc  = ks * 32 + ((lane >> 4) << 4);
            uint32_t sw = SMEM_SWIZZLE_128B((uint32_t)(row * 128 + bc));
            LDSM_X4(ah[t], sA_hi + sw);
            LDSM_X4(al[t], sA_lo + sw);
        }
#pragma unroll
        for (int half = 0; half < 2; half++) {
            uint32_t bh[2][4], bl[2][4];
#pragma unroll
            for (int q = 0; q < 2; q++) {
                int nbase = wn * 64 + half * 32 + q * 16;
                int row = nbase + (lane & 7) + ((lane >> 4) << 3);
                int bc  = ks * 32 + (((lane >> 3) & 1) << 4);
                uint32_t sw = SMEM_SWIZZLE_128B((uint32_t)(row * 128 + bc));
                LDSM_X4(bh[q], sB_hi + sw);
                LDSM_X4(bl[q], sB_lo + sw);
            }
#pragma unroll
            for (int t = 0; t < 2; t++) {
#pragma unroll
                for (int j = 0; j < 4; j++) {
                    int ntile = half * 4 + j;
                    uint32_t bh0 = bh[j >> 1][(j & 1) * 2];
                    uint32_t bh1 = bh[j >> 1][(j & 1) * 2 + 1];
                    uint32_t bl0 = bl[j >> 1][(j & 1) * 2];
                    uint32_t bl1 = bl[j >> 1][(j & 1) * 2 + 1];
                    MMA_BF16(acc[t][ntile], ah[t], bh0, bh1);
                    MMA_BF16(acc[t][ntile], ah[t], bl0, bl1);
                    MMA_BF16(acc[t][ntile], al[t], bh0, bh1);
                }
            }
        }
    }
}
#endif

// ================= main per-batch expert GEMM =================
__global__ void __launch_bounds__(NTHREADS, 1)
moe_gemm_kernel(const float* __restrict__ x,
                const float* __restrict__ be,
                float* __restrict__ out) {
    extern __shared__ char smem[];
    uint32_t smem_base = smem_to_u32(smem);
    int tid  = threadIdx.x;
    int wid  = tid >> 5;
    int lane = tid & 31;

    int bx = blockIdx.x;          // 4096 = B * 2(Mtiles) * 2(Ntiles)
    int b  = bx >> 2;
    int mt = (bx >> 1) & 1;
    int nt = bx & 1;
    int m0 = mt * BM;
    int n0 = nt * BN;

    int   e    = g_idx[b];
    float gate = g_gate[b];

    const float* xA = x + ((size_t)b * S_SZ + m0) * D_SZ;                 // [128, 512]
    const unsigned char* Bt_hi = g_Wt_hi + ((size_t)(e * 2 + nt) * KCHUNKS) * BTILE_BYTES;
    const unsigned char* Bt_lo = g_Wt_lo + ((size_t)(e * 2 + nt) * KCHUNKS) * BTILE_BYTES;

    const uint32_t stg_u32[2] = { smem_base + STAGE0_OFF,
                                  smem_base + STAGE0_OFF + STAGE_STRIDE };
    char* const stg_ptr[2] = { smem + STAGE0_OFF, smem + STAGE0_OFF + STAGE_STRIDE };

    if (tid < BN)
        *(float*)(smem + SMEM_BIAS + tid * 4) = be[(size_t)e * O_SZ + n0 + tid];

    // per-thread A load coordinates (fixed across chunks)
    int ar[4], acq[4];
#pragma unroll
    for (int i = 0; i < 4; i++) {
        int idx4 = tid + i * NTHREADS;
        ar[i]  = idx4 >> 4;      // A row 0..127
        acq[i] = idx4 & 15;      // float4 within row
    }

#if USE_TCGEN05
    // ================== tcgen05 path: bulk-copy B + register A, 2-stage pipeline ==================
    if (wid == 0) {
        TCGEN05_ALLOC(smem_base + SMEM_TMEM_PTR, 256);
        TCGEN05_RELINQUISH_ALLOC_PERMIT();
    }
    if (tid == 0) {
        MBARRIER_INIT(smem_base + SMEM_FULL0, NTHREADS + 1);   // 512 A arrives + 1 expect_tx
        MBARRIER_INIT(smem_base + SMEM_FULL1, NTHREADS + 1);
        MBARRIER_INIT(smem_base + SMEM_EMPTY0, 1);
        MBARRIER_INIT(smem_base + SMEM_EMPTY1, 1);
    }
    __syncthreads();

    uint32_t tmem_base;
    asm volatile("ld.shared.b32 %0, [%1];" : "=r"(tmem_base) : "r"(smem_base + SMEM_TMEM_PTR));

    uint64_t aHi[2], aLo[2], bHi[2], bLo[2];
#pragma unroll
    for (int s = 0; s < 2; s++) {
        aHi[s] = MAKE_SMEM_DESC(stg_u32[s] + OFF_AHI);
        aLo[s] = MAKE_SMEM_DESC(stg_u32[s] + OFF_ALO);
        bHi[s] = MAKE_SMEM_DESC(stg_u32[s] + OFF_BHI);
        bLo[s] = MAKE_SMEM_DESC(stg_u32[s] + OFF_BLO);
    }

    // register prefetch of chunk 0 A
    float4 av[4];
#pragma unroll
    for (int i = 0; i < 4; i++)
        av[i] = *(const float4*)(xA + (size_t)ar[i] * D_SZ + acq[i] * 4);

    for (int c = 0; c < KCHUNKS; c++) {
        int s = c & 1;
        int u = c >> 1;
        uint32_t full_mbar  = smem_base + (s ? SMEM_FULL1  : SMEM_FULL0);
        uint32_t empty_mbar = smem_base + (s ? SMEM_EMPTY1 : SMEM_EMPTY0);

        if (u >= 1) MBARRIER_WAIT_PARITY(empty_mbar, (u - 1) & 1);

        // elected thread: kick off B bulk copies for this chunk
        if (wid == 0) {
            if (elect_one_pred()) {
                MBARRIER_EXPECT_TX(full_mbar, 2 * BTILE_BYTES);
                CP_ASYNC_BULK_G2S(stg_u32[s] + OFF_BHI, Bt_hi + (size_t)c * BTILE_BYTES,
                                  BTILE_BYTES, full_mbar);
                CP_ASYNC_BULK_G2S(stg_u32[s] + OFF_BLO, Bt_lo + (size_t)c * BTILE_BYTES,
                                  BTILE_BYTES, full_mbar);
            }
        }

        // all threads: A convert + STS
        char* sp = stg_ptr[s];
#pragma unroll
        for (int i = 0; i < 4; i++) {
            __nv_bfloat16 h0 = __float2bfloat16(av[i].x);
            __nv_bfloat16 h1 = __float2bfloat16(av[i].y);
            __nv_bfloat16 h2 = __float2bfloat16(av[i].z);
            __nv_bfloat16 h3 = __float2bfloat16(av[i].w);
            __nv_bfloat16 l0 = __float2bfloat16(av[i].x - __bfloat162float(h0));
            __nv_bfloat16 l1 = __float2bfloat16(av[i].y - __bfloat162float(h1));
            __nv_bfloat16 l2 = __float2bfloat16(av[i].z - __bfloat162float(h2));
            __nv_bfloat16 l3 = __float2bfloat16(av[i].w - __bfloat162float(h3));
            uint32_t swa = SMEM_SWIZZLE_128B((uint32_t)(ar[i] * 128 + acq[i] * 8));
            *(uint2*)(sp + OFF_AHI + swa) = make_uint2(pack_bf16x2(h0, h1), pack_bf16x2(h2, h3));
            *(uint2*)(sp + OFF_ALO + swa) = make_uint2(pack_bf16x2(l0, l1), pack_bf16x2(l2, l3));
        }
        FENCE_PROXY_ASYNC_SHARED_CTA();
        MBARRIER_ARRIVE(full_mbar);

        // prefetch next chunk A (overlaps MMA of this chunk)
        if (c + 1 < KCHUNKS) {
            int k0 = (c + 1) * BK;
#pragma unroll
            for (int i = 0; i < 4; i++)
                av[i] = *(const float4*)(xA + (size_t)ar[i] * D_SZ + k0 + acq[i] * 4);
        }

        if (wid == 0) {
            if (elect_one_pred()) {
                MBARRIER_WAIT_PARITY(full_mbar, u & 1);
#pragma unroll
                for (int ks = 0; ks < 4; ks++) {
                    uint64_t ah = aHi[s] + ks * 2;
                    uint64_t al = aLo[s] + ks * 2;
                    uint64_t bh = bHi[s] + ks * 2;
                    uint64_t bl = bLo[s] + ks * 2;
                    bool first = (c == 0) && (ks == 0);
                    mma_f16_ss_cg1(tmem_base, ah, bh, MMA_IDESC, !first);
                    mma_f16_ss_cg1(tmem_base, ah, bl, MMA_IDESC, true);
                    mma_f16_ss_cg1(tmem_base, al, bh, MMA_IDESC, true);
                }
                TCGEN05_COMMIT(empty_mbar);
            }
        }
    }

    {   // drain
        int par = ((KCHUNKS / 2) - 1) & 1;
        MBARRIER_WAIT_PARITY(smem_base + SMEM_EMPTY0, par);
        MBARRIER_WAIT_PARITY(smem_base + SMEM_EMPTY1, par);
    }
    __syncthreads();
    TCGEN05_FENCE_AFTER();

    // ---- direct-register epilogue: 16 warps, each 32 rows x 64 cols ----
    {
        const float* biasp = (const float*)(smem + SMEM_BIAS);
        int sub  = wid & 3;
        int part = wid >> 2;
        int row  = sub * 32 + lane;
        float* orow = out + (((size_t)b * S_SZ + m0 + row) * O_SZ) + n0;
#pragma unroll
        for (int cc = 0; cc < 2; cc++) {
            int col0 = part * 64 + cc * 32;
            uint32_t regs[32];
            TCGEN05_LD_32X32B_X32(regs, tmem_base + col0);
            TCGEN05_WAIT_LD();
#pragma unroll
            for (int q = 0; q < 8; q++) {
                float4 v;
                v.x = gate * (__uint_as_float(regs[q * 4 + 0]) + biasp[col0 + q * 4 + 0]);
                v.y = gate * (__uint_as_float(regs[q * 4 + 1]) + biasp[col0 + q * 4 + 1]);
                v.z = gate * (__uint_as_float(regs[q * 4 + 2]) + biasp[col0 + q * 4 + 2]);
                v.w = gate * (__uint_as_float(regs[q * 4 + 3]) + biasp[col0 + q * 4 + 3]);
                *(float4*)(orow + col0 + q * 4) = v;
            }
        }
    }
    __syncthreads();
    if (wid == 0) TCGEN05_DEALLOC(tmem_base, 256);

#else
    // ================== fallback path: double-buffered mma.sync bf16 ==================
    int wm = wid & 3;
    int wn = wid >> 2;

    float acc[2][8][4];
#pragma unroll
    for (int i = 0; i < 2; i++)
#pragma unroll
        for (int j = 0; j < 8; j++)
#pragma unroll
            for (int q = 0; q < 4; q++) acc[i][j][q] = 0.f;

    float4 av[4];

    // ---- prologue: stage 0 (B blocks copied linearly: tiled layout == SMEM image) ----
    {
#pragma unroll
        for (int i = 0; i < 4; i++) {
            uint32_t off = (uint32_t)(tid * 16 + i * 8192);
            CP_ASYNC16(stg_u32[0] + OFF_BHI + off, Bt_hi + off);
            CP_ASYNC16(stg_u32[0] + OFF_BLO + off, Bt_lo + off);
        }
        CP_ASYNC_COMMIT();
#pragma unroll
        for (int i = 0; i < 4; i++)
            av[i] = *(const float4*)(xA + (size_t)ar[i] * D_SZ + acq[i] * 4);
#pragma unroll
        for (int i = 0; i < 4; i++) {
            __nv_bfloat16 h0 = __float2bfloat16(av[i].x);
            __nv_bfloat16 h1 = __float2bfloat16(av[i].y);
            __nv_bfloat16 h2 = __float2bfloat16(av[i].z);
            __nv_bfloat16 h3 = __float2bfloat16(av[i].w);
            __nv_bfloat16 l0 = __float2bfloat16(av[i].x - __bfloat162float(h0));
            __nv_bfloat16 l1 = __float2bfloat16(av[i].y - __bfloat162float(h1));
            __nv_bfloat16 l2 = __float2bfloat16(av[i].z - __bfloat162float(h2));
            __nv_bfloat16 l3 = __float2bfloat16(av[i].w - __bfloat162float(h3));
            uint32_t sw = SMEM_SWIZZLE_128B((uint32_t)(ar[i] * 128 + acq[i] * 8));
            *(uint2*)(stg_ptr[0] + OFF_AHI + sw) = make_uint2(pack_bf16x2(h0, h1), pack_bf16x2(h2, h3));
            *(uint2*)(stg_ptr[0] + OFF_ALO + sw) = make_uint2(pack_bf16x2(l0, l1), pack_bf16x2(l2, l3));
        }
        CP_ASYNC_WAIT_ALL();
        __syncthreads();
    }

    for (int c = 0; c < KCHUNKS; c++) {
        int cur = c & 1;
        int nxt = cur ^ 1;
        bool more = (c + 1 < KCHUNKS);

        if (more) {
            size_t blk = (size_t)(c + 1) * BTILE_BYTES;
#pragma unroll
            for (int i = 0; i < 4; i++) {
                uint32_t off = (uint32_t)(tid * 16 + i * 8192);
                CP_ASYNC16(stg_u32[nxt] + OFF_BHI + off, Bt_hi + blk + off);
                CP_ASYNC16(stg_u32[nxt] + OFF_BLO + off, Bt_lo + blk + off);
            }
            CP_ASYNC_COMMIT();
            int k0 = (c + 1) * BK;
#pragma unroll
            for (int i = 0; i < 4; i++)
                av[i] = *(const float4*)(xA + (size_t)ar[i] * D_SZ + k0 + acq[i] * 4);
        }

        fb_compute(stg_u32[cur] + OFF_AHI, stg_u32[cur] + OFF_ALO,
                   stg_u32[cur] + OFF_BHI, stg_u32[cur] + OFF_BLO,
                   lane, wm, wn, acc);

        if (more) {
#pragma unroll
            for (int i = 0; i < 4; i++) {
                __nv_bfloat16 h0 = __float2bfloat16(av[i].x);
                __nv_bfloat16 h1 = __float2bfloat16(av[i].y);
                __nv_bfloat16 h2 = __float2bfloat16(av[i].z);
                __nv_bfloat16 h3 = __float2bfloat16(av[i].w);
                __nv_bfloat16 l0 = __float2bfloat16(av[i].x - __bfloat162float(h0));
                __nv_bfloat16 l1 = __float2bfloat16(av[i].y - __bfloat162float(h1));
                __nv_bfloat16 l2 = __float2bfloat16(av[i].z - __bfloat162float(h2));
                __nv_bfloat16 l3 = __float2bfloat16(av[i].w - __bfloat162float(h3));
                uint32_t sw = SMEM_SWIZZLE_128B((uint32_t)(ar[i] * 128 + acq[i] * 8));
                *(uint2*)(stg_ptr[nxt] + OFF_AHI + sw) = make_uint2(pack_bf16x2(h0, h1), pack_bf16x2(h2, h3));
                *(uint2*)(stg_ptr[nxt] + OFF_ALO + sw) = make_uint2(pack_bf16x2(l0, l1), pack_bf16x2(l2, l3));
            }
            CP_ASYNC_WAIT_ALL();
        }
        __syncthreads();
    }

    // epilogue: direct register stores with gate*(acc+bias)
    const float* biasp = (const float*)(smem + SMEM_BIAS);
#pragma unroll
    for (int t = 0; t < 2; t++) {
#pragma unroll
        for (int j = 0; j < 8; j++) {
            int col = wn * 64 + j * 8 + (lane & 3) * 2;
            int r0  = m0 + wm * 32 + t * 16 + (lane >> 2);
            float b0v = biasp[col], b1v = biasp[col + 1];
            float2 v0, v1;
            v0.x = gate * (acc[t][j][0] + b0v);
            v0.y = gate * (acc[t][j][1] + b1v);
            v1.x = gate * (acc[t][j][2] + b0v);
            v1.y = gate * (acc[t][j][3] + b1v);
            *(float2*)(out + ((size_t)b * S_SZ + r0) * O_SZ + n0 + col)       = v0;
            *(float2*)(out + ((size_t)b * S_SZ + r0 + 8) * O_SZ + n0 + col)   = v1;
        }
    }
#endif
}

// ================= launch =================
extern "C" void kernel_launch(void* const* d_in, const int* in_sizes, int n_in,
                              void* d_out, int out_size) {
    const float* x  = (const float*)d_in[0];
    const float* Wg = (const float*)d_in[1];
    const float* bg = (const float*)d_in[2];
    const float* We = (const float*)d_in[3];
    const float* be = (const float*)d_in[4];
    float* out = (float*)d_out;

    gating_kernel<<<B_SZ, 512>>>(x, Wg, bg);

    dim3 cgrid(O_SZ / 32, D_SZ / 32, E_SZ);
    convert_w_kernel<<<cgrid, dim3(32, 8)>>>(We);

    cudaFuncSetAttribute(moe_gemm_kernel,
                         cudaFuncAttributeMaxDynamicSharedMemorySize, SMEM_TOTAL);
    moe_gemm_kernel<<<B_SZ * 4, NTHREADS, SMEM_TOTAL>>>(x, be, out);
}

// round 6
// speedup vs baseline: 1.4117x; 1.4117x over previous
#include <cuda_runtime.h>
#include <cuda_bf16.h>
#include <cstdint>

#define B_SZ 1024
#define S_SZ 256
#define D_SZ 512
#define E_SZ 16
#define O_SZ 512

#define BM 128
#define BN 256
#define BK 64
#define KCHUNKS (D_SZ / BK)
#define NTHREADS 512
#define BTILE_BYTES 32768      /* 256 rows x 128B, SW128 image of one (ntile, kchunk) */

// Feature gate: defined only when codegen targets sm_103a (arch-specific pass).
#if defined(__CUDA_ARCH__) && (defined(__CUDA_ARCH_FEAT_SM103_ALL) || \
    (defined(__CUDA_ARCH_SPECIFIC__) && (__CUDA_ARCH_SPECIFIC__ == 1030)))
#define USE_TCGEN05 1
#else
#define USE_TCGEN05 0
#endif

// ---------------- scratch (device globals; no allocation allowed) ----------------
__device__ __align__(128) unsigned char g_Wt_hi[E_SZ * 2 * KCHUNKS * BTILE_BYTES];
__device__ __align__(128) unsigned char g_Wt_lo[E_SZ * 2 * KCHUNKS * BTILE_BYTES];
__device__ int   g_idx[B_SZ];
__device__ float g_gate[B_SZ];

// ---------------- common helpers ----------------
__device__ __forceinline__ uint32_t smem_to_u32(const void* p) {
    uint32_t a;
    asm("{ .reg .u64 t; cvta.to.shared.u64 t, %1; cvt.u32.u64 %0, t; }" : "=r"(a) : "l"(p));
    return a;
}
#define SMEM_SWIZZLE_128B(o) ((o) ^ (((o) >> 3) & 0x70))

__device__ __forceinline__ uint32_t pack_bf16x2(__nv_bfloat16 a, __nv_bfloat16 b) {
    uint16_t au = __bfloat16_as_ushort(a);
    uint16_t bu = __bfloat16_as_ushort(b);
    return (uint32_t)au | ((uint32_t)bu << 16);
}

#define CP_ASYNC16(dst_u32, src_ptr) \
    asm volatile("cp.async.cg.shared.global [%0], [%1], 16;" :: "r"(dst_u32), "l"(src_ptr))
#define CP_ASYNC_COMMIT() asm volatile("cp.async.commit_group;" ::: "memory")
#define CP_ASYNC_WAIT_ALL() asm volatile("cp.async.wait_group 0;" ::: "memory")

// ---------------- SMEM layouts ----------------
// tc kernel (single 96KB stage, occ 2):
#define TC_TMEM_PTR 0
#define TC_FULL     16
#define TC_EMPTY    24
#define TC_STAGE    1024
#define TC_AHI      0
#define TC_ALO      16384
#define TC_BHI      32768
#define TC_BLO      65536
#define TC_BIAS     (TC_STAGE + 98304)          // 99328
#define TC_SMEM_TOTAL (TC_BIAS + 1024 + 128)    // 100480  -> 2 CTAs/SM

// fb kernel (two 96KB stages, occ 1):
#define FB_STAGE0_OFF    1024
#define FB_STAGE_STRIDE  98304
#define FB_AHI       0
#define FB_ALO       16384
#define FB_BHI       32768
#define FB_BLO       65536
#define FB_BIAS     (FB_STAGE0_OFF + 2 * FB_STAGE_STRIDE)   // 197632
#define FB_SMEM_TOTAL (FB_BIAS + 1024 + 128)                // 198784

#if USE_TCGEN05
// ---------------- tcgen05 PTX helpers (sm_103a pass only) ----------------
__device__ __forceinline__ uint32_t elect_one_pred() {
    uint32_t pred;
    asm volatile(
        "{\n\t.reg .pred p;\n\t"
        "elect.sync _|p, 0xFFFFFFFF;\n\t"
        "selp.b32 %0, 1, 0, p;\n\t}"
        : "=r"(pred));
    return pred;
}
static constexpr uint64_t SMEM_DESC_BASE_SW128 =
    (uint64_t(2)  << 61) | (uint64_t(1) << 46) | (uint64_t(64) << 32) | (uint64_t(1) << 16);
#define MAKE_SMEM_DESC(base_addr) \
    (SMEM_DESC_BASE_SW128 | ((uint64_t)((base_addr) >> 4) & 0x3FFF))

#define TCGEN05_ALLOC(smem_result_addr, nCols) \
    asm volatile("tcgen05.alloc.cta_group::1.sync.aligned.shared::cta.b32 [%0], %1;" \
        :: "r"((uint32_t)(smem_result_addr)), "r"((uint32_t)(nCols)) : "memory")
#define TCGEN05_DEALLOC(tmem_addr, nCols) \
    asm volatile("tcgen05.dealloc.cta_group::1.sync.aligned.b32 %0, %1;" \
        :: "r"(tmem_addr), "r"((uint32_t)(nCols)))
#define TCGEN05_RELINQUISH_ALLOC_PERMIT() \
    asm volatile("tcgen05.relinquish_alloc_permit.cta_group::1.sync.aligned;")
#define TCGEN05_COMMIT(mbar_smem_addr) \
    asm volatile("tcgen05.commit.cta_group::1.mbarrier::arrive::one.shared::cluster.b64 [%0];" \
        :: "r"((uint32_t)(mbar_smem_addr)) : "memory")
#define TCGEN05_FENCE_AFTER() \
    asm volatile("tcgen05.fence::after_thread_sync;" ::: "memory")
#define TCGEN05_WAIT_LD() \
    asm volatile("tcgen05.wait::ld.sync.aligned;" ::: "memory")
#define FENCE_PROXY_ASYNC_SHARED_CTA() \
    asm volatile("fence.proxy.async.shared::cta;" ::: "memory")
#define MBARRIER_INIT(mbar_smem_addr, count) \
    asm volatile("mbarrier.init.shared.b64 [%0], %1;" \
        :: "r"((uint32_t)(mbar_smem_addr)), "r"((uint32_t)(count)) : "memory")
#define MBARRIER_ARRIVE(mbar_smem_addr) \
    asm volatile("mbarrier.arrive.shared.b64 _, [%0];" \
        :: "r"((uint32_t)(mbar_smem_addr)) : "memory")
#define MBARRIER_EXPECT_TX(mbar_smem_addr, tx_bytes) \
    asm volatile("mbarrier.arrive.expect_tx.shared.b64 _, [%0], %1;" \
        :: "r"((uint32_t)(mbar_smem_addr)), "r"((uint32_t)(tx_bytes)) : "memory")
#define CP_ASYNC_BULK_G2S(dst_u32, src_ptr, bytes, mbar) \
    asm volatile("cp.async.bulk.shared::cta.global.mbarrier::complete_tx::bytes [%0], [%1], %2, [%3];" \
        :: "r"((uint32_t)(dst_u32)), "l"(src_ptr), "r"((uint32_t)(bytes)), "r"((uint32_t)(mbar)) : "memory")
#define MBARRIER_WAIT_PARITY(mbar_smem_addr, phase_parity) do { \
    uint32_t _mbar = (uint32_t)(mbar_smem_addr); \
    uint32_t _parity = (uint32_t)(phase_parity); \
    uint32_t _done; \
    asm volatile( \
        "{\n\t.reg .pred p;\n\t" \
        "mbarrier.try_wait.parity.acquire.cta.shared::cta.b64 p, [%1], %2;\n\t" \
        "selp.b32 %0, 1, 0, p;\n\t}" \
        : "=r"(_done) : "r"(_mbar), "r"(_parity) : "memory"); \
    if (!_done) { \
        asm volatile( \
            "{\n\t.reg .pred P1;\n\t" \
            "WAIT_LOOP_%=:\n\t" \
            "mbarrier.try_wait.parity.acquire.cta.shared::cta.b64 P1, [%0], %1, 0x989680;\n\t" \
            "@P1 bra.uni WAIT_DONE_%=;\n\t" \
            "bra.uni WAIT_LOOP_%=;\n\t" \
            "WAIT_DONE_%=:\n\t}" \
            :: "r"(_mbar), "r"(_parity) : "memory"); \
    } \
} while(0)
#define TCGEN05_LD_32X32B_X32(r, tmem_addr) \
    asm volatile( \
        "tcgen05.ld.sync.aligned.32x32b.x32.b32 " \
        "{%0, %1, %2, %3, %4, %5, %6, %7, " \
        " %8, %9, %10, %11, %12, %13, %14, %15, " \
        " %16, %17, %18, %19, %20, %21, %22, %23, " \
        " %24, %25, %26, %27, %28, %29, %30, %31}, [%32];" \
        : "=r"((r)[0]),  "=r"((r)[1]),  "=r"((r)[2]),  "=r"((r)[3]), \
          "=r"((r)[4]),  "=r"((r)[5]),  "=r"((r)[6]),  "=r"((r)[7]), \
          "=r"((r)[8]),  "=r"((r)[9]),  "=r"((r)[10]), "=r"((r)[11]), \
          "=r"((r)[12]), "=r"((r)[13]), "=r"((r)[14]), "=r"((r)[15]), \
          "=r"((r)[16]), "=r"((r)[17]), "=r"((r)[18]), "=r"((r)[19]), \
          "=r"((r)[20]), "=r"((r)[21]), "=r"((r)[22]), "=r"((r)[23]), \
          "=r"((r)[24]), "=r"((r)[25]), "=r"((r)[26]), "=r"((r)[27]), \
          "=r"((r)[28]), "=r"((r)[29]), "=r"((r)[30]), "=r"((r)[31]) \
        : "r"(tmem_addr))

__device__ __forceinline__ void mma_f16_ss_cg1(uint32_t d_tmem, uint64_t a_desc,
                                               uint64_t b_desc, uint32_t idesc, bool acc) {
    uint32_t en = acc ? 1u : 0u;
    asm volatile(
        "{\n\t.reg .pred p;\n\t"
        "setp.ne.u32 p, %5, 0;\n\t"
        "tcgen05.mma.cta_group::1.kind::f16 [%0], %1, %2, %3, {%4, %4, %4, %4}, p;\n\t}"
        :: "r"(d_tmem), "l"(a_desc), "l"(b_desc), "r"(idesc), "r"(0u), "r"(en)
        : "memory");
}
static constexpr uint32_t MMA_IDESC =
    (1u << 4) | (1u << 7) | (1u << 10) | ((BN / 8) << 17) | ((BM / 16) << 24);
#endif  // USE_TCGEN05

// ---------------- fallback helpers (legal on plain sm_103) ----------------
#define LDSM_X4(r, addr) \
    asm volatile("ldmatrix.sync.aligned.m8n8.x4.shared.b16 {%0,%1,%2,%3}, [%4];" \
        : "=r"((r)[0]), "=r"((r)[1]), "=r"((r)[2]), "=r"((r)[3]) : "r"(addr))

#define MMA_BF16(d, a, b0, b1) \
    asm volatile("mma.sync.aligned.m16n8k16.row.col.f32.bf16.bf16.f32 " \
        "{%0,%1,%2,%3}, {%4,%5,%6,%7}, {%8,%9}, {%0,%1,%2,%3};" \
        : "+f"((d)[0]), "+f"((d)[1]), "+f"((d)[2]), "+f"((d)[3]) \
        : "r"((a)[0]), "r"((a)[1]), "r"((a)[2]), "r"((a)[3]), "r"(b0), "r"(b1))

// ================= probe: detects which cubin (103a vs 103) is loaded =================
__global__ void probe_kernel(int* p) {
#if USE_TCGEN05
    __shared__ int dummy[1024];
    dummy[threadIdx.x & 1023] = (int)threadIdx.x;
    __syncthreads();
    if (p) *p = dummy[0];
#else
    if (p) *p = 0;
#endif
}

// ================= gating: mean -> linear -> softmax -> argmax =================
__global__ void __launch_bounds__(512)
gating_kernel(const float* __restrict__ x,
              const float* __restrict__ Wg,
              const float* __restrict__ bg) {
    int b = blockIdx.x;
    int tid = threadIdx.x;
    __shared__ float4 part[4][128];
    __shared__ float xm[D_SZ];
    __shared__ float logits[E_SZ];

    int grp = tid >> 7;
    int dq  = tid & 127;

    const float4* xp = reinterpret_cast<const float4*>(x + (size_t)b * S_SZ * D_SZ)
                       + (size_t)grp * (D_SZ / 4) + dq;
    float4 a = make_float4(0.f, 0.f, 0.f, 0.f);
#pragma unroll 16
    for (int s = 0; s < S_SZ / 4; s++) {
        float4 v = xp[(size_t)s * D_SZ];
        a.x += v.x; a.y += v.y; a.z += v.z; a.w += v.w;
    }
    part[grp][dq] = a;
    __syncthreads();

    if (tid < 128) {
        float4 p0 = part[0][tid], p1 = part[1][tid], p2 = part[2][tid], p3 = part[3][tid];
        const float inv = 1.0f / S_SZ;
        xm[tid * 4 + 0] = (p0.x + p1.x + p2.x + p3.x) * inv;
        xm[tid * 4 + 1] = (p0.y + p1.y + p2.y + p3.y) * inv;
        xm[tid * 4 + 2] = (p0.z + p1.z + p2.z + p3.z) * inv;
        xm[tid * 4 + 3] = (p0.w + p1.w + p2.w + p3.w) * inv;
    }
    __syncthreads();

    int wid = tid >> 5, lane = tid & 31;
    float p = 0.f;
    for (int d = lane; d < D_SZ; d += 32) p += xm[d] * Wg[d * E_SZ + wid];
#pragma unroll
    for (int o = 16; o; o >>= 1) p += __shfl_xor_sync(0xffffffffu, p, o);
    if (lane == 0) logits[wid] = p + bg[wid];
    __syncthreads();

    if (tid == 0) {
        float mx = logits[0]; int mi = 0;
#pragma unroll
        for (int e = 1; e < E_SZ; e++) if (logits[e] > mx) { mx = logits[e]; mi = e; }
        float den = 0.f;
#pragma unroll
        for (int e = 0; e < E_SZ; e++) den += expf(logits[e] - mx);
        g_idx[b]  = mi;
        g_gate[b] = 1.0f / den;
    }
}

// ====== convert We[E,D,O] fp32 -> tiled pre-swizzled bf16 hi/lo blocks ======
__global__ void convert_w_kernel(const float* __restrict__ We) {
    __shared__ float tile[32][33];
    int e  = blockIdx.z;
    int d0 = blockIdx.y * 32;
    int o0 = blockIdx.x * 32;
    int tx = threadIdx.x, ty = threadIdx.y;

    const float* src = We + ((size_t)e * D_SZ + d0) * O_SZ + o0;
#pragma unroll
    for (int k = 0; k < 4; k++)
        tile[ty + 8 * k][tx] = src[(size_t)(ty + 8 * k) * O_SZ + tx];
    __syncthreads();

#pragma unroll
    for (int k = 0; k < 4; k++) {
        float v = tile[tx][ty + 8 * k];
        __nv_bfloat16 hi = __float2bfloat16(v);
        float r = v - __bfloat162float(hi);
        __nv_bfloat16 lo = __float2bfloat16(r);

        int o  = o0 + ty + 8 * k;
        int d  = d0 + tx;
        int nt = o >> 8;
        int rr = o & 255;
        int c  = d >> 6;
        int dk = d & 63;
        size_t block = ((size_t)(e * 2 + nt) * KCHUNKS + c) * BTILE_BYTES;
        uint32_t off = SMEM_SWIZZLE_128B((uint32_t)(rr * 128 + dk * 2));
        *(__nv_bfloat16*)(g_Wt_hi + block + off) = hi;
        *(__nv_bfloat16*)(g_Wt_lo + block + off) = lo;
    }
}

// ================= tc GEMM: single-stage, occ-2, bulk-B, mbarrier pipeline =================
__global__ void __launch_bounds__(NTHREADS, 2)
moe_gemm_tc(const float* __restrict__ x,
            const float* __restrict__ be,
            float* __restrict__ out) {
#if USE_TCGEN05
    extern __shared__ char smem[];
    uint32_t smem_base = smem_to_u32(smem);
    int tid  = threadIdx.x;
    int wid  = tid >> 5;
    int lane = tid & 31;

    int bx = blockIdx.x;
    int b  = bx >> 2;
    int mt = (bx >> 1) & 1;
    int nt = bx & 1;
    int m0 = mt * BM;
    int n0 = nt * BN;

    int   e    = g_idx[b];
    float gate = g_gate[b];

    const float* xA = x + ((size_t)b * S_SZ + m0) * D_SZ;
    const unsigned char* Bt_hi = g_Wt_hi + ((size_t)(e * 2 + nt) * KCHUNKS) * BTILE_BYTES;
    const unsigned char* Bt_lo = g_Wt_lo + ((size_t)(e * 2 + nt) * KCHUNKS) * BTILE_BYTES;

    if (wid == 0) {
        TCGEN05_ALLOC(smem_base + TC_TMEM_PTR, 256);
        TCGEN05_RELINQUISH_ALLOC_PERMIT();
    }
    if (tid == 0) {
        MBARRIER_INIT(smem_base + TC_FULL, NTHREADS + 1);   // 512 arrives + 1 expect_tx arrive
        MBARRIER_INIT(smem_base + TC_EMPTY, 1);             // tcgen05.commit
    }
    if (tid < BN)
        *(float*)(smem + TC_BIAS + tid * 4) = be[(size_t)e * O_SZ + n0 + tid];
    __syncthreads();

    uint32_t tmem_base;
    asm volatile("ld.shared.b32 %0, [%1];" : "=r"(tmem_base) : "r"(smem_base + TC_TMEM_PTR));

    const uint64_t aHi = MAKE_SMEM_DESC(smem_base + TC_STAGE + TC_AHI);
    const uint64_t aLo = MAKE_SMEM_DESC(smem_base + TC_STAGE + TC_ALO);
    const uint64_t bHi = MAKE_SMEM_DESC(smem_base + TC_STAGE + TC_BHI);
    const uint64_t bLo = MAKE_SMEM_DESC(smem_base + TC_STAGE + TC_BLO);

    int ar[4], acq[4];
#pragma unroll
    for (int i = 0; i < 4; i++) {
        int idx4 = tid + i * NTHREADS;
        ar[i]  = idx4 >> 4;
        acq[i] = idx4 & 15;
    }

    // register prefetch chunk 0 A
    float4 av[4];
#pragma unroll
    for (int i = 0; i < 4; i++)
        av[i] = *(const float4*)(xA + (size_t)ar[i] * D_SZ + acq[i] * 4);

    char* sp = smem + TC_STAGE;
    for (int c = 0; c < KCHUNKS; c++) {
        // wait for MMA of chunk c-1 to finish before overwriting the stage
        if (c > 0) MBARRIER_WAIT_PARITY(smem_base + TC_EMPTY, (c - 1) & 1);

        if (wid == 0) {
            if (elect_one_pred()) {
                MBARRIER_EXPECT_TX(smem_base + TC_FULL, 2 * BTILE_BYTES);
                CP_ASYNC_BULK_G2S(smem_base + TC_STAGE + TC_BHI,
                                  Bt_hi + (size_t)c * BTILE_BYTES, BTILE_BYTES,
                                  smem_base + TC_FULL);
                CP_ASYNC_BULK_G2S(smem_base + TC_STAGE + TC_BLO,
                                  Bt_lo + (size_t)c * BTILE_BYTES, BTILE_BYTES,
                                  smem_base + TC_FULL);
            }
        }

#pragma unroll
        for (int i = 0; i < 4; i++) {
            __nv_bfloat16 h0 = __float2bfloat16(av[i].x);
            __nv_bfloat16 h1 = __float2bfloat16(av[i].y);
            __nv_bfloat16 h2 = __float2bfloat16(av[i].z);
            __nv_bfloat16 h3 = __float2bfloat16(av[i].w);
            __nv_bfloat16 l0 = __float2bfloat16(av[i].x - __bfloat162float(h0));
            __nv_bfloat16 l1 = __float2bfloat16(av[i].y - __bfloat162float(h1));
            __nv_bfloat16 l2 = __float2bfloat16(av[i].z - __bfloat162float(h2));
            __nv_bfloat16 l3 = __float2bfloat16(av[i].w - __bfloat162float(h3));
            uint32_t swa = SMEM_SWIZZLE_128B((uint32_t)(ar[i] * 128 + acq[i] * 8));
            *(uint2*)(sp + TC_AHI + swa) = make_uint2(pack_bf16x2(h0, h1), pack_bf16x2(h2, h3));
            *(uint2*)(sp + TC_ALO + swa) = make_uint2(pack_bf16x2(l0, l1), pack_bf16x2(l2, l3));
        }
        FENCE_PROXY_ASYNC_SHARED_CTA();
        MBARRIER_ARRIVE(smem_base + TC_FULL);

        // prefetch next chunk A (overlaps the copy + MMA)
        if (c + 1 < KCHUNKS) {
            int k0 = (c + 1) * BK;
#pragma unroll
            for (int i = 0; i < 4; i++)
                av[i] = *(const float4*)(xA + (size_t)ar[i] * D_SZ + k0 + acq[i] * 4);
        }

        if (wid == 0) {
            if (elect_one_pred()) {
                MBARRIER_WAIT_PARITY(smem_base + TC_FULL, c & 1);
#pragma unroll
                for (int ks = 0; ks < 4; ks++) {
                    uint64_t ah = aHi + ks * 2;
                    uint64_t al = aLo + ks * 2;
                    uint64_t bh = bHi + ks * 2;
                    uint64_t bl = bLo + ks * 2;
                    bool first = (c == 0) && (ks == 0);
                    mma_f16_ss_cg1(tmem_base, ah, bh, MMA_IDESC, !first);
                    mma_f16_ss_cg1(tmem_base, ah, bl, MMA_IDESC, true);
                    mma_f16_ss_cg1(tmem_base, al, bh, MMA_IDESC, true);
                }
                TCGEN05_COMMIT(smem_base + TC_EMPTY);
            }
        }
    }

    MBARRIER_WAIT_PARITY(smem_base + TC_EMPTY, (KCHUNKS - 1) & 1);
    __syncthreads();
    TCGEN05_FENCE_AFTER();

    // ---- direct-register epilogue ----
    {
        const float* biasp = (const float*)(smem + TC_BIAS);
        int sub  = wid & 3;
        int part = wid >> 2;
        int row  = sub * 32 + lane;
        float* orow = out + (((size_t)b * S_SZ + m0 + row) * O_SZ) + n0;
#pragma unroll
        for (int cc = 0; cc < 2; cc++) {
            int col0 = part * 64 + cc * 32;
            uint32_t regs[32];
            TCGEN05_LD_32X32B_X32(regs, tmem_base + col0);
            TCGEN05_WAIT_LD();
#pragma unroll
            for (int q = 0; q < 8; q++) {
                float4 v;
                v.x = gate * (__uint_as_float(regs[q * 4 + 0]) + biasp[col0 + q * 4 + 0]);
                v.y = gate * (__uint_as_float(regs[q * 4 + 1]) + biasp[col0 + q * 4 + 1]);
                v.z = gate * (__uint_as_float(regs[q * 4 + 2]) + biasp[col0 + q * 4 + 2]);
                v.w = gate * (__uint_as_float(regs[q * 4 + 3]) + biasp[col0 + q * 4 + 3]);
                *(float4*)(orow + col0 + q * 4) = v;
            }
        }
    }
    __syncthreads();
    if (wid == 0) TCGEN05_DEALLOC(tmem_base, 256);
#endif  // USE_TCGEN05 (else: never launched on this cubin)
}

// ================= fb GEMM: double-buffered mma.sync bf16 (R4/R5 proven) =================
#if !USE_TCGEN05
__device__ __forceinline__ void fb_compute(uint32_t sA_hi, uint32_t sA_lo,
                                           uint32_t sB_hi, uint32_t sB_lo,
                                           int lane, int wm, int wn,
                                           float acc[2][8][4]) {
#pragma unroll
    for (int ks = 0; ks < 4; ks++) {
        uint32_t ah[2][4], al[2][4];
#pragma unroll
        for (int t = 0; t < 2; t++) {
            int row = wm * 32 + t * 16 + (lane & 15);
            int bc  = ks * 32 + ((lane >> 4) << 4);
            uint32_t sw = SMEM_SWIZZLE_128B((uint32_t)(row * 128 + bc));
            LDSM_X4(ah[t], sA_hi + sw);
            LDSM_X4(al[t], sA_lo + sw);
        }
#pragma unroll
        for (int half = 0; half < 2; half++) {
            uint32_t bh[2][4], bl[2][4];
#pragma unroll
            for (int q = 0; q < 2; q++) {
                int nbase = wn * 64 + half * 32 + q * 16;
                int row = nbase + (lane & 7) + ((lane >> 4) << 3);
                int bc  = ks * 32 + (((lane >> 3) & 1) << 4);
                uint32_t sw = SMEM_SWIZZLE_128B((uint32_t)(row * 128 + bc));
                LDSM_X4(bh[q], sB_hi + sw);
                LDSM_X4(bl[q], sB_lo + sw);
            }
#pragma unroll
            for (int t = 0; t < 2; t++) {
#pragma unroll
                for (int j = 0; j < 4; j++) {
                    int ntile = half * 4 + j;
                    uint32_t bh0 = bh[j >> 1][(j & 1) * 2];
                    uint32_t bh1 = bh[j >> 1][(j & 1) * 2 + 1];
                    uint32_t bl0 = bl[j >> 1][(j & 1) * 2];
                    uint32_t bl1 = bl[j >> 1][(j & 1) * 2 + 1];
                    MMA_BF16(acc[t][ntile], ah[t], bh0, bh1);
                    MMA_BF16(acc[t][ntile], ah[t], bl0, bl1);
                    MMA_BF16(acc[t][ntile], al[t], bh0, bh1);
                }
            }
        }
    }
}
#endif

__global__ void __launch_bounds__(NTHREADS, 1)
moe_gemm_fb(const float* __restrict__ x,
            const float* __restrict__ be,
            float* __restrict__ out) {
#if !USE_TCGEN05
    extern __shared__ char smem[];
    uint32_t smem_base = smem_to_u32(smem);
    int tid  = threadIdx.x;
    int wid  = tid >> 5;
    int lane = tid & 31;

    int bx = blockIdx.x;
    int b  = bx >> 2;
    int mt = (bx >> 1) & 1;
    int nt = bx & 1;
    int m0 = mt * BM;
    int n0 = nt * BN;

    int   e    = g_idx[b];
    float gate = g_gate[b];

    const float* xA = x + ((size_t)b * S_SZ + m0) * D_SZ;
    const unsigned char* Bt_hi = g_Wt_hi + ((size_t)(e * 2 + nt) * KCHUNKS) * BTILE_BYTES;
    const unsigned char* Bt_lo = g_Wt_lo + ((size_t)(e * 2 + nt) * KCHUNKS) * BTILE_BYTES;

    const uint32_t stg_u32[2] = { smem_base + FB_STAGE0_OFF,
                                  smem_base + FB_STAGE0_OFF + FB_STAGE_STRIDE };
    char* const stg_ptr[2] = { smem + FB_STAGE0_OFF, smem + FB_STAGE0_OFF + FB_STAGE_STRIDE };

    if (tid < BN)
        *(float*)(smem + FB_BIAS + tid * 4) = be[(size_t)e * O_SZ + n0 + tid];

    int ar[4], acq[4];
#pragma unroll
    for (int i = 0; i < 4; i++) {
        int idx4 = tid + i * NTHREADS;
        ar[i]  = idx4 >> 4;
        acq[i] = idx4 & 15;
    }

    int wm = wid & 3;
    int wn = wid >> 2;

    float acc[2][8][4];
#pragma unroll
    for (int i = 0; i < 2; i++)
#pragma unroll
        for (int j = 0; j < 8; j++)
#pragma unroll
            for (int q = 0; q < 4; q++) acc[i][j][q] = 0.f;

    float4 av[4];

    // prologue: stage 0
    {
#pragma unroll
        for (int i = 0; i < 4; i++) {
            uint32_t off = (uint32_t)(tid * 16 + i * 8192);
            CP_ASYNC16(stg_u32[0] + FB_BHI + off, Bt_hi + off);
            CP_ASYNC16(stg_u32[0] + FB_BLO + off, Bt_lo + off);
        }
        CP_ASYNC_COMMIT();
#pragma unroll
        for (int i = 0; i < 4; i++)
            av[i] = *(const float4*)(xA + (size_t)ar[i] * D_SZ + acq[i] * 4);
#pragma unroll
        for (int i = 0; i < 4; i++) {
            __nv_bfloat16 h0 = __float2bfloat16(av[i].x);
            __nv_bfloat16 h1 = __float2bfloat16(av[i].y);
            __nv_bfloat16 h2 = __float2bfloat16(av[i].z);
            __nv_bfloat16 h3 = __float2bfloat16(av[i].w);
            __nv_bfloat16 l0 = __float2bfloat16(av[i].x - __bfloat162float(h0));
            __nv_bfloat16 l1 = __float2bfloat16(av[i].y - __bfloat162float(h1));
            __nv_bfloat16 l2 = __float2bfloat16(av[i].z - __bfloat162float(h2));
            __nv_bfloat16 l3 = __float2bfloat16(av[i].w - __bfloat162float(h3));
            uint32_t sw = SMEM_SWIZZLE_128B((uint32_t)(ar[i] * 128 + acq[i] * 8));
            *(uint2*)(stg_ptr[0] + FB_AHI + sw) = make_uint2(pack_bf16x2(h0, h1), pack_bf16x2(h2, h3));
            *(uint2*)(stg_ptr[0] + FB_ALO + sw) = make_uint2(pack_bf16x2(l0, l1), pack_bf16x2(l2, l3));
        }
        CP_ASYNC_WAIT_ALL();
        __syncthreads();
    }

    for (int c = 0; c < KCHUNKS; c++) {
        int cur = c & 1;
        int nxt = cur ^ 1;
        bool more = (c + 1 < KCHUNKS);

        if (more) {
            size_t blk = (size_t)(c + 1) * BTILE_BYTES;
#pragma unroll
            for (int i = 0; i < 4; i++) {
                uint32_t off = (uint32_t)(tid * 16 + i * 8192);
                CP_ASYNC16(stg_u32[nxt] + FB_BHI + off, Bt_hi + blk + off);
                CP_ASYNC16(stg_u32[nxt] + FB_BLO + off, Bt_lo + blk + off);
            }
            CP_ASYNC_COMMIT();
            int k0 = (c + 1) * BK;
#pragma unroll
            for (int i = 0; i < 4; i++)
                av[i] = *(const float4*)(xA + (size_t)ar[i] * D_SZ + k0 + acq[i] * 4);
        }

        fb_compute(stg_u32[cur] + FB_AHI, stg_u32[cur] + FB_ALO,
                   stg_u32[cur] + FB_BHI, stg_u32[cur] + FB_BLO,
                   lane, wm, wn, acc);

        if (more) {
#pragma unroll
            for (int i = 0; i < 4; i++) {
                __nv_bfloat16 h0 = __float2bfloat16(av[i].x);
                __nv_bfloat16 h1 = __float2bfloat16(av[i].y);
                __nv_bfloat16 h2 = __float2bfloat16(av[i].z);
                __nv_bfloat16 h3 = __float2bfloat16(av[i].w);
                __nv_bfloat16 l0 = __float2bfloat16(av[i].x - __bfloat162float(h0));
                __nv_bfloat16 l1 = __float2bfloat16(av[i].y - __bfloat162float(h1));
                __nv_bfloat16 l2 = __float2bfloat16(av[i].z - __bfloat162float(h2));
                __nv_bfloat16 l3 = __float2bfloat16(av[i].w - __bfloat162float(h3));
                uint32_t sw = SMEM_SWIZZLE_128B((uint32_t)(ar[i] * 128 + acq[i] * 8));
                *(uint2*)(stg_ptr[nxt] + FB_AHI + sw) = make_uint2(pack_bf16x2(h0, h1), pack_bf16x2(h2, h3));
                *(uint2*)(stg_ptr[nxt] + FB_ALO + sw) = make_uint2(pack_bf16x2(l0, l1), pack_bf16x2(l2, l3));
            }
            CP_ASYNC_WAIT_ALL();
        }
        __syncthreads();
    }

    const float* biasp = (const float*)(smem + FB_BIAS);
#pragma unroll
    for (int t = 0; t < 2; t++) {
#pragma unroll
        for (int j = 0; j < 8; j++) {
            int col = wn * 64 + j * 8 + (lane & 3) * 2;
            int r0  = m0 + wm * 32 + t * 16 + (lane >> 2);
            float b0v = biasp[col], b1v = biasp[col + 1];
            float2 v0, v1;
            v0.x = gate * (acc[t][j][0] + b0v);
            v0.y = gate * (acc[t][j][1] + b1v);
            v1.x = gate * (acc[t][j][2] + b0v);
            v1.y = gate * (acc[t][j][3] + b1v);
            *(float2*)(out + ((size_t)b * S_SZ + r0) * O_SZ + n0 + col)       = v0;
            *(float2*)(out + ((size_t)b * S_SZ + r0 + 8) * O_SZ + n0 + col)   = v1;
        }
    }
#endif  // !USE_TCGEN05 (else: never launched on this cubin)
}

// ================= launch =================
extern "C" void kernel_launch(void* const* d_in, const int* in_sizes, int n_in,
                              void* d_out, int out_size) {
    const float* x  = (const float*)d_in[0];
    const float* Wg = (const float*)d_in[1];
    const float* bg = (const float*)d_in[2];
    const float* We = (const float*)d_in[3];
    const float* be = (const float*)d_in[4];
    float* out = (float*)d_out;

    // which cubin is loaded? (attribute query; not a stream op; deterministic)
    cudaFuncAttributes pa;
    cudaFuncGetAttributes(&pa, probe_kernel);
    bool tc_live = (pa.sharedSizeBytes >= 4096);

    gating_kernel<<<B_SZ, 512>>>(x, Wg, bg);

    dim3 cgrid(O_SZ / 32, D_SZ / 32, E_SZ);
    convert_w_kernel<<<cgrid, dim3(32, 8)>>>(We);

    if (tc_live) {
        cudaFuncSetAttribute(moe_gemm_tc,
                             cudaFuncAttributeMaxDynamicSharedMemorySize, TC_SMEM_TOTAL);
        moe_gemm_tc<<<B_SZ * 4, NTHREADS, TC_SMEM_TOTAL>>>(x, be, out);
    } else {
        cudaFuncSetAttribute(moe_gemm_fb,
                             cudaFuncAttributeMaxDynamicSharedMemorySize, FB_SMEM_TOTAL);
        moe_gemm_fb<<<B_SZ * 4, NTHREADS, FB_SMEM_TOTAL>>>(x, be, out);
    }
}